// round 1
// baseline (speedup 1.0000x reference)
#include <cuda_runtime.h>
#include <math.h>
#include <stdint.h>

#define BB  32
#define MM  65536
#define WD  32
#define RR  4
#define KK  16
#define CC  65
#define INS 256
#define NEG_INF (-3.402823e38f)

// ---------------- scratch (device globals; no allocation allowed) ----------------
__device__ __align__(16) float g_scores[BB * RR * MM];   // 33.5 MB score buffer
__device__ __align__(16) float g_rq[BB * RR * WD];       // read queries
__device__ __align__(16) float g_newvis[BB * CC * WD];   // updated memory rows
__device__ float g_newusage[BB * CC];                    // scattered usage values
__device__ int   g_least[BB];                            // argmin(updated usage)
__device__ int   g_topk[BB * RR * KK];                   // top-16 indices per (b,r)

// ---------------- kernel 1: projections + write-phase (per batch) ----------------
__global__ void k_setup(const float* __restrict__ xi,
                        const float* __restrict__ rw,
                        const float* __restrict__ ww,
                        const float* __restrict__ usage,
                        const float* __restrict__ vis,
                        const float* __restrict__ Wrq, const float* __restrict__ brq,
                        const float* __restrict__ Wwv, const float* __restrict__ bwv,
                        const float* __restrict__ Wig, const float* __restrict__ big,
                        const float* __restrict__ Wwg, const float* __restrict__ bwg,
                        const int* __restrict__ rpos,
                        const int* __restrict__ tptr)
{
    int b = blockIdx.x;
    int t = threadIdx.x;

    __shared__ float s_xi[INS];
    __shared__ float s_wv[WD];
    __shared__ float s_ig[CC];
    __shared__ float s_wg;
    __shared__ float s_ru[CC], s_rwg[CC], s_wwg[CC], s_I[CC], s_wwn[CC];
    __shared__ float s_minu;
    __shared__ int   s_p[CC];

    s_xi[t] = xi[b * INS + t];
    __syncthreads();

    // 226 tiny dot products of length 256
    if (t < 226) {
        const float* wrow;
        float bias;
        if (t < 128)      { wrow = Wrq + t * INS;         bias = brq[t]; }
        else if (t < 160) { wrow = Wwv + (t - 128) * INS; bias = bwv[t - 128]; }
        else if (t < 225) { wrow = Wig + (t - 160) * INS; bias = big[t - 160]; }
        else              { wrow = Wwg;                   bias = bwg[0]; }
        float acc = bias;
#pragma unroll 8
        for (int j = 0; j < INS; j++) acc += s_xi[j] * wrow[j];
        if (t < 128)      g_rq[b * 128 + t] = acc;
        else if (t < 160) s_wv[t - 128] = acc;
        else if (t < 225) s_ig[t - 160] = 1.0f / (1.0f + expf(-acc));
        else              s_wg          = 1.0f / (1.0f + expf(-acc));
    }

    int ts = tptr ? *tptr : 2;

    if (t < CC) {
        int p = rpos[b * CC + t];
        s_p[t] = p;
        float rg = rw[(size_t)b * MM + p];
        if (ts == 1) rg += 1.0f;
        s_rwg[t] = rg;
        s_wwg[t] = ww[(size_t)b * MM + p];
        s_ru[t]  = usage[(size_t)b * MM + p];
    }
    __syncthreads();
    if (t == 0) {
        float mn = s_ru[0];
        for (int c = 1; c < CC; c++) mn = fminf(mn, s_ru[c]);
        s_minu = mn;
    }
    __syncthreads();
    if (t < CC) {
        float I = (s_ru[t] == s_minu) ? 1.0f : 0.0f;
        s_I[t] = I;
        float u = ((s_rwg[t] + s_wwg[t]) > 0.005f) ? 1.0f : 0.0f;
        float nru = (u > 0.0f) ? ((float)ts - s_ru[t]) : s_ru[t];
        g_newusage[b * CC + t] = nru;
        s_wwn[t] = s_wg * (s_ig[t] * s_rwg[t] + (1.0f - s_ig[t]) * I);
    }
    __syncthreads();
    // updated visible rows (= values scattered into memory)
    for (int idx = t; idx < CC * WD; idx += blockDim.x) {
        int c = idx >> 5, w = idx & 31;
        float nv = vis[(size_t)b * CC * WD + idx] * (1.0f - s_I[c]) + s_wwn[c] * s_wv[w];
        g_newvis[(size_t)b * CC * WD + idx] = nv;
    }
}

// ---------------- kernel 2: argmin over updated usage (per batch) ----------------
__global__ void k_argmin(const float* __restrict__ usage,
                         const int* __restrict__ rpos)
{
    int b = blockIdx.x;
    int t = threadIdx.x;          // 256 threads
    __shared__ unsigned s_bm[MM / 32];  // 8 KB bitmap
    __shared__ int   s_p[CC];
    __shared__ float s_nu[CC];
    __shared__ float s_v[256];
    __shared__ int   s_i[256];

    for (int i = t; i < MM / 32; i += 256) s_bm[i] = 0u;
    if (t < CC) { s_p[t] = rpos[b * CC + t]; s_nu[t] = g_newusage[b * CC + t]; }
    __syncthreads();
    if (t < CC) atomicOr(&s_bm[s_p[t] >> 5], 1u << (s_p[t] & 31));
    __syncthreads();

    float bv = 3.402823e38f;
    int   bi = 0;
    for (int m = t; m < MM; m += 256) {
        float v = usage[(size_t)b * MM + m];
        if ((s_bm[m >> 5] >> (m & 31)) & 1u) {
            for (int c = CC - 1; c >= 0; c--)      // last write wins
                if (s_p[c] == m) { v = s_nu[c]; break; }
        }
        if (v < bv) { bv = v; bi = m; }            // strict < keeps first index
    }
    s_v[t] = bv; s_i[t] = bi;
    __syncthreads();
    for (int s = 128; s > 0; s >>= 1) {
        if (t < s) {
            if (s_v[t + s] < s_v[t] || (s_v[t + s] == s_v[t] && s_i[t + s] < s_i[t])) {
                s_v[t] = s_v[t + s]; s_i[t] = s_i[t + s];
            }
        }
        __syncthreads();
    }
    if (t == 0) g_least[b] = s_i[0];
}

// ---------------- kernel 3: streaming scores (HBM-bound main pass) ----------------
__global__ void k_scores(const float* __restrict__ memory,
                         const int* __restrict__ rpos)
{
    int b = blockIdx.y;
    int chunk = blockIdx.x;       // 16 chunks of 4096 rows
    int t = threadIdx.x;          // 256 threads

    __shared__ unsigned s_bm[MM / 32];  // 8 KB
    __shared__ int   s_p[CC];
    __shared__ float s_q[RR * WD];

    for (int i = t; i < MM / 32; i += 256) s_bm[i] = 0u;
    if (t < CC)       s_p[t] = rpos[b * CC + t];
    if (t < RR * WD)  s_q[t] = g_rq[b * RR * WD + t];
    __syncthreads();
    if (t < CC) atomicOr(&s_bm[s_p[t] >> 5], 1u << (s_p[t] & 31));
    __syncthreads();

    int base = chunk * 4096;
    for (int i = 0; i < 16; i++) {
        int m = base + i * 256 + t;
        const float4* row;
        if ((s_bm[m >> 5] >> (m & 31)) & 1u) {
            int cc = CC - 1;
            for (; cc >= 0; cc--) if (s_p[cc] == m) break;
            row = (const float4*)(g_newvis + ((size_t)b * CC + cc) * WD);
        } else {
            row = (const float4*)(memory + ((size_t)b * MM + m) * WD);
        }
        float a0 = 0.f, a1 = 0.f, a2 = 0.f, a3 = 0.f;
#pragma unroll
        for (int j = 0; j < 8; j++) {
            float4 v = row[j];
            int o = j * 4;
            a0 += v.x * s_q[o]      + v.y * s_q[o + 1]      + v.z * s_q[o + 2]      + v.w * s_q[o + 3];
            a1 += v.x * s_q[32 + o] + v.y * s_q[33 + o]     + v.z * s_q[34 + o]     + v.w * s_q[35 + o];
            a2 += v.x * s_q[64 + o] + v.y * s_q[65 + o]     + v.z * s_q[66 + o]     + v.w * s_q[67 + o];
            a3 += v.x * s_q[96 + o] + v.y * s_q[97 + o]     + v.z * s_q[98 + o]     + v.w * s_q[99 + o];
        }
        size_t ob = (size_t)b * RR * MM + m;
        g_scores[ob]          = a0;
        g_scores[ob + MM]     = a1;
        g_scores[ob + 2 * MM] = a2;
        g_scores[ob + 3 * MM] = a3;
    }
}

// ---------------- kernel 4: top-16 per (b, r) ----------------
__global__ void k_topk()
{
    __shared__ float s_cv[256 * 17];   // padded stride 17 -> no bank conflicts
    __shared__ int   s_ci[256 * 17];
    __shared__ float s_rv[256];
    __shared__ int   s_ri[256];

    int br = blockIdx.x;   // b*R + r
    int t  = threadIdx.x;  // 256 threads
    float* cv = s_cv + t * 17;
    int*   ci = s_ci + t * 17;
#pragma unroll
    for (int j = 0; j < KK; j++) { cv[j] = NEG_INF; ci[j] = 0; }

    const float* sc = g_scores + (size_t)br * MM;
    float cmin = NEG_INF;
    for (int m = t; m < MM; m += 256) {
        float v = sc[m];
        if (v > cmin) {
            int j = 0;
#pragma unroll
            for (int jj = 0; jj < KK - 1; jj++) {
                if (cv[jj + 1] < v) { cv[jj] = cv[jj + 1]; ci[jj] = ci[jj + 1]; j = jj + 1; }
                else break;
            }
            cv[j] = v; ci[j] = m;
            cmin = cv[0];
        }
    }

    int p = KK - 1;
    __syncthreads();
    for (int round = 0; round < KK; round++) {
        s_rv[t] = (p >= 0) ? cv[p] : NEG_INF;
        s_ri[t] = t;
        __syncthreads();
        for (int s = 128; s > 0; s >>= 1) {
            if (t < s) {
                if (s_rv[t + s] > s_rv[t] ||
                    (s_rv[t + s] == s_rv[t] && s_ri[t + s] < s_ri[t])) {
                    s_rv[t] = s_rv[t + s]; s_ri[t] = s_ri[t + s];
                }
            }
            __syncthreads();
        }
        if (t == s_ri[0]) { g_topk[br * KK + round] = ci[p]; p--; }
        __syncthreads();
    }
}

// ---------------- kernel 5: gather + cosine softmax + read vectors ----------------
__global__ void k_final(const float* __restrict__ memory,
                        const int* __restrict__ rpos,
                        float* __restrict__ out)
{
    int b = blockIdx.x;
    int t = threadIdx.x;   // 128 threads

    __shared__ int   s_pos[CC];
    __shared__ int   s_rp[CC];
    __shared__ float s_vm[CC * 33];   // padded rows
    __shared__ float s_norm[CC];
    __shared__ float s_q[RR * WD];
    __shared__ float s_kn[RR];
    __shared__ float s_wt[RR * CC];

    s_q[t] = g_rq[b * RR * WD + t];
    if (t < RR * KK) s_pos[t] = g_topk[b * RR * KK + t];
    if (t == 0)      s_pos[CC - 1] = g_least[b];
    if (t < CC)      s_rp[t] = rpos[b * CC + t];
    __syncthreads();

    if (t < RR) {
        float s = 0.f;
        for (int w = 0; w < WD; w++) { float q = s_q[t * WD + w]; s += q * q; }
        s_kn[t] = sqrtf(s) + 1e-6f;
    }
    if (t < CC) {
        int m = s_pos[t];
        m = min(max(m, 0), MM - 1);
        const float* row = memory + ((size_t)b * MM + m) * WD;
        for (int c2 = CC - 1; c2 >= 0; c2--)      // override with updated rows
            if (s_rp[c2] == m) { row = g_newvis + ((size_t)b * CC + c2) * WD; break; }
        float s = 0.f;
        for (int w = 0; w < WD; w++) { float v = row[w]; s_vm[t * 33 + w] = v; s += v * v; }
        s_norm[t] = sqrtf(s) + 1e-6f;
    }
    __syncthreads();

    for (int idx = t; idx < RR * CC; idx += 128) {
        int r = idx / CC, c = idx % CC;
        float num = 0.f;
        for (int w = 0; w < WD; w++) num += s_vm[c * 33 + w] * s_q[r * WD + w];
        s_wt[idx] = num / ((float)WD * s_norm[c] * s_kn[r] + 1e-6f);
    }
    __syncthreads();

    if (t < RR) {
        float mx = NEG_INF;
        for (int c = 0; c < CC; c++) mx = fmaxf(mx, s_wt[t * CC + c]);
        float sum = 0.f;
        for (int c = 0; c < CC; c++) { float e = expf(s_wt[t * CC + c] - mx); s_wt[t * CC + c] = e; sum += e; }
        float inv = 1.0f / sum;
        for (int c = 0; c < CC; c++) s_wt[t * CC + c] *= inv;
    }
    __syncthreads();

    {
        int r = t >> 5, w = t & 31;
        float acc = 0.f;
        for (int c = 0; c < CC; c++) acc += s_wt[r * CC + c] * s_vm[c * 33 + w];
        out[b * RR * WD + t] = acc;
    }
}

// ---------------- launch ----------------
extern "C" void kernel_launch(void* const* d_in, const int* in_sizes, int n_in,
                              void* d_out, int out_size)
{
    const float* xi     = (const float*)d_in[0];
    const float* memory = (const float*)d_in[1];
    const float* rw     = (const float*)d_in[2];
    const float* ww     = (const float*)d_in[3];
    const float* usage  = (const float*)d_in[4];
    const float* vis    = (const float*)d_in[5];
    const float* Wrq    = (const float*)d_in[6];
    const float* brq    = (const float*)d_in[7];
    const float* Wwv    = (const float*)d_in[8];
    const float* bwv    = (const float*)d_in[9];
    const float* Wig    = (const float*)d_in[10];
    const float* big    = (const float*)d_in[11];
    const float* Wwg    = (const float*)d_in[12];
    const float* bwg    = (const float*)d_in[13];
    const int*   rpos   = (const int*)d_in[14];
    // d_in[15] = least_used_mem input: dead in the reference (recomputed before use)
    const int*   tptr   = (n_in > 16) ? (const int*)d_in[16] : nullptr;

    k_setup<<<BB, 256>>>(xi, rw, ww, usage, vis, Wrq, brq, Wwv, bwv,
                         Wig, big, Wwg, bwg, rpos, tptr);
    k_argmin<<<BB, 256>>>(usage, rpos);
    dim3 gs(16, BB);
    k_scores<<<gs, 256>>>(memory, rpos);
    k_topk<<<BB * RR, 256>>>();
    k_final<<<BB, 128>>>(memory, rpos, (float*)d_out);
}

// round 2
// speedup vs baseline: 2.6971x; 2.6971x over previous
#include <cuda_runtime.h>
#include <math.h>
#include <stdint.h>

#define BB  32
#define MM  65536
#define WD  32
#define RR  4
#define KK  16
#define CC  65
#define INS 256
#define NEG_INF (-3.402823e38f)
#define POS_INF ( 3.402823e38f)

// ---------------- scratch (device globals; no allocation allowed) ----------------
__device__ __align__(16) float g_scores[BB * RR * MM];     // 33.5 MB score buffer
__device__ __align__(16) float g_rq[BB * RR * WD];         // read queries
__device__ __align__(16) float g_newvis[BB * CC * WD];     // updated memory rows
__device__ float g_newusage[BB * CC];                      // scattered usage values
__device__ int   g_least[BB];                              // argmin(updated usage)
__device__ int   g_topk[BB * RR * KK];                     // top-16 indices per (b,r)
// segmented top-k candidates: per (b,r): 16 segs * 8 warps * 16 = 2048
__device__ __align__(16) float g_cand_v[BB * RR * 2048];
__device__ __align__(16) int   g_cand_i[BB * RR * 2048];
// segmented argmin partials: per b: 16 segments
__device__ float g_seg_minv[BB * 16];
__device__ int   g_seg_mini[BB * 16];

// ---------------- kernel 1: projections + write-phase (per batch) ----------------
__global__ void k_setup(const float* __restrict__ xi,
                        const float* __restrict__ rw,
                        const float* __restrict__ ww,
                        const float* __restrict__ usage,
                        const float* __restrict__ vis,
                        const float* __restrict__ Wrq, const float* __restrict__ brq,
                        const float* __restrict__ Wwv, const float* __restrict__ bwv,
                        const float* __restrict__ Wig, const float* __restrict__ big,
                        const float* __restrict__ Wwg, const float* __restrict__ bwg,
                        const int* __restrict__ rpos,
                        const int* __restrict__ tptr)
{
    int b = blockIdx.x;
    int t = threadIdx.x;

    __shared__ float s_xi[INS];
    __shared__ float s_wv[WD];
    __shared__ float s_ig[CC];
    __shared__ float s_wg;
    __shared__ float s_ru[CC], s_rwg[CC], s_wwg[CC], s_I[CC], s_wwn[CC];
    __shared__ float s_minu;
    __shared__ int   s_p[CC];

    s_xi[t] = xi[b * INS + t];
    __syncthreads();

    if (t < 226) {
        const float* wrow;
        float bias;
        if (t < 128)      { wrow = Wrq + t * INS;         bias = brq[t]; }
        else if (t < 160) { wrow = Wwv + (t - 128) * INS; bias = bwv[t - 128]; }
        else if (t < 225) { wrow = Wig + (t - 160) * INS; bias = big[t - 160]; }
        else              { wrow = Wwg;                   bias = bwg[0]; }
        float acc = bias;
#pragma unroll 8
        for (int j = 0; j < INS; j++) acc += s_xi[j] * wrow[j];
        if (t < 128)      g_rq[b * 128 + t] = acc;
        else if (t < 160) s_wv[t - 128] = acc;
        else if (t < 225) s_ig[t - 160] = 1.0f / (1.0f + expf(-acc));
        else              s_wg          = 1.0f / (1.0f + expf(-acc));
    }

    int ts = tptr ? *tptr : 2;

    if (t < CC) {
        int p = rpos[b * CC + t];
        s_p[t] = p;
        float rg = rw[(size_t)b * MM + p];
        if (ts == 1) rg += 1.0f;
        s_rwg[t] = rg;
        s_wwg[t] = ww[(size_t)b * MM + p];
        s_ru[t]  = usage[(size_t)b * MM + p];
    }
    __syncthreads();
    if (t == 0) {
        float mn = s_ru[0];
        for (int c = 1; c < CC; c++) mn = fminf(mn, s_ru[c]);
        s_minu = mn;
    }
    __syncthreads();
    if (t < CC) {
        float I = (s_ru[t] == s_minu) ? 1.0f : 0.0f;
        s_I[t] = I;
        float u = ((s_rwg[t] + s_wwg[t]) > 0.005f) ? 1.0f : 0.0f;
        float nru = (u > 0.0f) ? ((float)ts - s_ru[t]) : s_ru[t];
        g_newusage[b * CC + t] = nru;
        s_wwn[t] = s_wg * (s_ig[t] * s_rwg[t] + (1.0f - s_ig[t]) * I);
    }
    __syncthreads();
    for (int idx = t; idx < CC * WD; idx += blockDim.x) {
        int c = idx >> 5, w = idx & 31;
        float nv = vis[(size_t)b * CC * WD + idx] * (1.0f - s_I[c]) + s_wwn[c] * s_wv[w];
        g_newvis[(size_t)b * CC * WD + idx] = nv;
    }
}

// ---------------- kernel 2: branch-free streaming scores ----------------
__global__ void k_scores(const float* __restrict__ memory)
{
    int b = blockIdx.y;
    int t = threadIdx.x;          // 256 threads

    __shared__ float4 s_q4[RR * 8];
    if (t < RR * 8) s_q4[t] = ((const float4*)g_rq)[b * RR * 8 + t];
    __syncthreads();

    int base = blockIdx.x * 4096;  // 16 chunks of 4096 rows
#pragma unroll 2
    for (int i = 0; i < 8; i++) {
        int m0 = base + i * 256 + t;
        int m1 = m0 + 2048;
        const float4* r0 = (const float4*)(memory + ((size_t)b * MM + m0) * WD);
        const float4* r1 = (const float4*)(memory + ((size_t)b * MM + m1) * WD);
        float a0[4] = {0.f, 0.f, 0.f, 0.f};
        float a1[4] = {0.f, 0.f, 0.f, 0.f};
#pragma unroll
        for (int j = 0; j < 8; j++) {
            float4 x0 = r0[j];
            float4 x1 = r1[j];
#pragma unroll
            for (int r = 0; r < 4; r++) {
                float4 q = s_q4[r * 8 + j];
                a0[r] += x0.x * q.x + x0.y * q.y + x0.z * q.z + x0.w * q.w;
                a1[r] += x1.x * q.x + x1.y * q.y + x1.z * q.z + x1.w * q.w;
            }
        }
#pragma unroll
        for (int r = 0; r < 4; r++) {
            g_scores[((size_t)b * RR + r) * MM + m0] = a0[r];
            g_scores[((size_t)b * RR + r) * MM + m1] = a1[r];
        }
    }
}

// ---------------- kernel 2b: overwrite scores at the 65 updated rows ----------------
__global__ void k_fixup(const int* __restrict__ rpos)
{
    int b = blockIdx.x;
    int t = threadIdx.x;   // 320 threads, 260 active

    __shared__ float s_q[RR * WD];
    __shared__ int   s_p[CC];
    if (t < RR * WD) s_q[t] = g_rq[b * RR * WD + t];
    if (t < CC)      s_p[t] = rpos[b * CC + t];
    __syncthreads();

    if (t < CC * RR) {
        int c = t >> 2, r = t & 3;
        bool last = true;
        for (int c2 = c + 1; c2 < CC; c2++) if (s_p[c2] == s_p[c]) { last = false; break; }
        if (last) {
            const float* row = g_newvis + ((size_t)b * CC + c) * WD;
            float acc = 0.f;
#pragma unroll
            for (int w = 0; w < WD; w++) acc += row[w] * s_q[r * WD + w];
            g_scores[((size_t)b * RR + r) * MM + s_p[c]] = acc;
        }
    }
}

// ---------------- kernel 3: segmented argmin over updated usage ----------------
__global__ void k_argmin_seg(const float* __restrict__ usage,
                             const int* __restrict__ rpos)
{
    int seg = blockIdx.x;  // 16 segments of 4096
    int b   = blockIdx.y;
    int t = threadIdx.x;   // 256
    int w = t >> 5, l = t & 31;

    __shared__ unsigned s_bm[128];   // 4096-bit exclusion bitmap
    __shared__ float s_wv[8];
    __shared__ int   s_wi[8];

    if (t < 128) s_bm[t] = 0u;
    __syncthreads();
    int segbase = seg * 4096;
    if (t < CC) {
        int p = rpos[b * CC + t];
        if (p >= segbase && p < segbase + 4096) {
            int loc = p - segbase;
            atomicOr(&s_bm[loc >> 5], 1u << (loc & 31));
        }
    }
    __syncthreads();

    const float4* u4 = (const float4*)(usage + (size_t)b * MM + segbase);
    float bv = POS_INF;
    int   bi = 0x7fffffff;
#pragma unroll
    for (int i = 0; i < 4; i++) {
        float4 x = u4[i * 256 + t];
        int lbase = (i * 256 + t) << 2;
        float xs[4] = {x.x, x.y, x.z, x.w};
#pragma unroll
        for (int j = 0; j < 4; j++) {
            int loc = lbase + j;
            float v = xs[j];
            if ((s_bm[loc >> 5] >> (loc & 31)) & 1u) v = POS_INF;
            int gi = segbase + loc;
            if (v < bv || (v == bv && gi < bi)) { bv = v; bi = gi; }
        }
    }
#pragma unroll
    for (int off = 16; off; off >>= 1) {
        float ov = __shfl_down_sync(0xffffffffu, bv, off);
        int   oi = __shfl_down_sync(0xffffffffu, bi, off);
        if (ov < bv || (ov == bv && oi < bi)) { bv = ov; bi = oi; }
    }
    if (l == 0) { s_wv[w] = bv; s_wi[w] = bi; }
    __syncthreads();
    if (t < 32) {
        float v = (l < 8) ? s_wv[l] : POS_INF;
        int   i = (l < 8) ? s_wi[l] : 0x7fffffff;
#pragma unroll
        for (int off = 4; off; off >>= 1) {
            float ov = __shfl_down_sync(0xffffffffu, v, off);
            int   oi = __shfl_down_sync(0xffffffffu, i, off);
            if (ov < v || (ov == v && oi < i)) { v = ov; i = oi; }
        }
        if (l == 0) { g_seg_minv[b * 16 + seg] = v; g_seg_mini[b * 16 + seg] = i; }
    }
}

// ---------------- kernel 3b: combine segment minima + overridden values ----------------
__global__ void k_argmin_combine(const int* __restrict__ rpos)
{
    int b = blockIdx.x;
    int t = threadIdx.x;   // 128

    __shared__ int   s_p[CC];
    __shared__ float s_v[128];
    __shared__ int   s_i[128];

    if (t < CC) s_p[t] = rpos[b * CC + t];
    __syncthreads();

    float v = POS_INF;
    int   i = 0x7fffffff;
    if (t < 16) { v = g_seg_minv[b * 16 + t]; i = g_seg_mini[b * 16 + t]; }
    else if (t < 16 + CC) {
        int c = t - 16;
        int p = s_p[c];
        bool last = true;
        for (int c2 = c + 1; c2 < CC; c2++) if (s_p[c2] == p) { last = false; break; }
        if (last) { v = g_newusage[b * CC + c]; i = p; }
    }
    s_v[t] = v; s_i[t] = i;
    __syncthreads();
    for (int s = 64; s > 0; s >>= 1) {
        if (t < s) {
            if (s_v[t + s] < s_v[t] || (s_v[t + s] == s_v[t] && s_i[t + s] < s_i[t])) {
                s_v[t] = s_v[t + s]; s_i[t] = s_i[t + s];
            }
        }
        __syncthreads();
    }
    if (t == 0) g_least[b] = s_i[0];
}

// ---------------- kernel 4: segmented warp-local top-16 ----------------
__global__ void k_topk_seg()
{
    int seg = blockIdx.x;   // 16 segments of 4096
    int br  = blockIdx.y;   // b*R + r
    int t = threadIdx.x;    // 256 = 8 warps, each warp owns 512 elements
    int w = t >> 5, l = t & 31;

    const float4* sc = (const float4*)(g_scores + (size_t)br * MM);
    int warpbase = seg * 4096 + w * 512;
    int fb = warpbase >> 2;

    float v[16];
#pragma unroll
    for (int i = 0; i < 4; i++) {
        float4 x = sc[fb + i * 32 + l];
        v[i * 4 + 0] = x.x; v[i * 4 + 1] = x.y; v[i * 4 + 2] = x.z; v[i * 4 + 3] = x.w;
    }

    float* outv = g_cand_v + ((size_t)br * 16 + seg) * 128 + w * 16;
    int*   outi = g_cand_i + ((size_t)br * 16 + seg) * 128 + w * 16;

    for (int round = 0; round < KK; round++) {
        float bv = v[0];
        int   bs = 0;
#pragma unroll
        for (int s = 1; s < 16; s++) if (v[s] > bv) { bv = v[s]; bs = s; }
        int bi = warpbase + ((bs >> 2) * 32 + l) * 4 + (bs & 3);
#pragma unroll
        for (int off = 16; off; off >>= 1) {
            float ov = __shfl_down_sync(0xffffffffu, bv, off);
            int   oi = __shfl_down_sync(0xffffffffu, bi, off);
            if (ov > bv || (ov == bv && oi < bi)) { bv = ov; bi = oi; }
        }
        bv = __shfl_sync(0xffffffffu, bv, 0);
        bi = __shfl_sync(0xffffffffu, bi, 0);
        if (l == 0) { outv[round] = bv; outi[round] = bi; }
        // remove winner from owner's registers
        int loc = bi - warpbase;
        int fidx = loc >> 2;
        if ((fidx & 31) == l) {
            int s = ((fidx >> 5) << 2) | (loc & 3);
#pragma unroll
            for (int ss = 0; ss < 16; ss++) if (ss == s) v[ss] = NEG_INF;
        }
    }
}

// ---------------- kernel 4b: merge 2048 candidates -> top-16 per (b,r) ----------------
__global__ void k_topk_merge()
{
    int br = blockIdx.x;    // 128
    int t = threadIdx.x;    // 256
    int w = t >> 5, l = t & 31;

    __shared__ float s_v[8];
    __shared__ int   s_i[8];
    __shared__ int   s_wi;

    float v[8];
    int   id[8];
    const float* cv = g_cand_v + (size_t)br * 2048;
    const int*   ci = g_cand_i + (size_t)br * 2048;
#pragma unroll
    for (int k = 0; k < 8; k++) { v[k] = cv[k * 256 + t]; id[k] = ci[k * 256 + t]; }

    for (int round = 0; round < KK; round++) {
        float bv = v[0];
        int   bi = id[0];
#pragma unroll
        for (int k = 1; k < 8; k++)
            if (v[k] > bv || (v[k] == bv && id[k] < bi)) { bv = v[k]; bi = id[k]; }
#pragma unroll
        for (int off = 16; off; off >>= 1) {
            float ov = __shfl_down_sync(0xffffffffu, bv, off);
            int   oi = __shfl_down_sync(0xffffffffu, bi, off);
            if (ov > bv || (ov == bv && oi < bi)) { bv = ov; bi = oi; }
        }
        if (l == 0) { s_v[w] = bv; s_i[w] = bi; }
        __syncthreads();
        if (t < 32) {
            float mv = (l < 8) ? s_v[l] : NEG_INF;
            int   mi = (l < 8) ? s_i[l] : 0x7fffffff;
#pragma unroll
            for (int off = 4; off; off >>= 1) {
                float ov = __shfl_down_sync(0xffffffffu, mv, off);
                int   oi = __shfl_down_sync(0xffffffffu, mi, off);
                if (ov > mv || (ov == mv && oi < mi)) { mv = ov; mi = oi; }
            }
            if (l == 0) { s_wi = mi; g_topk[br * KK + round] = mi; }
        }
        __syncthreads();
        int wi = s_wi;
#pragma unroll
        for (int k = 0; k < 8; k++) if (id[k] == wi) v[k] = NEG_INF;
        __syncthreads();
    }
}

// ---------------- kernel 5: gather + cosine softmax + read vectors ----------------
__global__ void k_final(const float* __restrict__ memory,
                        const int* __restrict__ rpos,
                        float* __restrict__ out)
{
    int b = blockIdx.x;
    int t = threadIdx.x;   // 128 threads

    __shared__ int   s_pos[CC];
    __shared__ int   s_rp[CC];
    __shared__ float s_vm[CC * 33];
    __shared__ float s_norm[CC];
    __shared__ float s_q[RR * WD];
    __shared__ float s_kn[RR];
    __shared__ float s_wt[RR * CC];

    s_q[t] = g_rq[b * RR * WD + t];
    if (t < RR * KK) s_pos[t] = g_topk[b * RR * KK + t];
    if (t == 0)      s_pos[CC - 1] = g_least[b];
    if (t < CC)      s_rp[t] = rpos[b * CC + t];
    __syncthreads();

    if (t < RR) {
        float s = 0.f;
        for (int w = 0; w < WD; w++) { float q = s_q[t * WD + w]; s += q * q; }
        s_kn[t] = sqrtf(s) + 1e-6f;
    }
    if (t < CC) {
        int m = s_pos[t];
        m = min(max(m, 0), MM - 1);
        const float* row = memory + ((size_t)b * MM + m) * WD;
        for (int c2 = CC - 1; c2 >= 0; c2--)
            if (s_rp[c2] == m) { row = g_newvis + ((size_t)b * CC + c2) * WD; break; }
        float s = 0.f;
        for (int w = 0; w < WD; w++) { float v = row[w]; s_vm[t * 33 + w] = v; s += v * v; }
        s_norm[t] = sqrtf(s) + 1e-6f;
    }
    __syncthreads();

    for (int idx = t; idx < RR * CC; idx += 128) {
        int r = idx / CC, c = idx % CC;
        float num = 0.f;
        for (int w = 0; w < WD; w++) num += s_vm[c * 33 + w] * s_q[r * WD + w];
        s_wt[idx] = num / ((float)WD * s_norm[c] * s_kn[r] + 1e-6f);
    }
    __syncthreads();

    if (t < RR) {
        float mx = NEG_INF;
        for (int c = 0; c < CC; c++) mx = fmaxf(mx, s_wt[t * CC + c]);
        float sum = 0.f;
        for (int c = 0; c < CC; c++) { float e = expf(s_wt[t * CC + c] - mx); s_wt[t * CC + c] = e; sum += e; }
        float inv = 1.0f / sum;
        for (int c = 0; c < CC; c++) s_wt[t * CC + c] *= inv;
    }
    __syncthreads();

    {
        int r = t >> 5, w = t & 31;
        float acc = 0.f;
        for (int c = 0; c < CC; c++) acc += s_wt[r * CC + c] * s_vm[c * 33 + w];
        out[b * RR * WD + t] = acc;
    }
}

// ---------------- launch ----------------
extern "C" void kernel_launch(void* const* d_in, const int* in_sizes, int n_in,
                              void* d_out, int out_size)
{
    const float* xi     = (const float*)d_in[0];
    const float* memory = (const float*)d_in[1];
    const float* rw     = (const float*)d_in[2];
    const float* ww     = (const float*)d_in[3];
    const float* usage  = (const float*)d_in[4];
    const float* vis    = (const float*)d_in[5];
    const float* Wrq    = (const float*)d_in[6];
    const float* brq    = (const float*)d_in[7];
    const float* Wwv    = (const float*)d_in[8];
    const float* bwv    = (const float*)d_in[9];
    const float* Wig    = (const float*)d_in[10];
    const float* big    = (const float*)d_in[11];
    const float* Wwg    = (const float*)d_in[12];
    const float* bwg    = (const float*)d_in[13];
    const int*   rpos   = (const int*)d_in[14];
    const int*   tptr   = (n_in > 16) ? (const int*)d_in[16] : nullptr;

    k_setup<<<BB, 256>>>(xi, rw, ww, usage, vis, Wrq, brq, Wwv, bwv,
                         Wig, big, Wwg, bwg, rpos, tptr);
    k_scores<<<dim3(16, BB), 256>>>(memory);
    k_fixup<<<BB, 320>>>(rpos);
    k_argmin_seg<<<dim3(16, BB), 256>>>(usage, rpos);
    k_argmin_combine<<<BB, 128>>>(rpos);
    k_topk_seg<<<dim3(16, BB * RR), 256>>>();
    k_topk_merge<<<BB * RR, 256>>>();
    k_final<<<BB, 128>>>(memory, rpos, (float*)d_out);
}

// round 3
// speedup vs baseline: 3.3714x; 1.2500x over previous
#include <cuda_runtime.h>
#include <math.h>
#include <stdint.h>

#define BB  32
#define MM  65536
#define WD  32
#define RR  4
#define KK  16
#define CC  65
#define INS 256
#define NEG_INF (-3.402823e38f)
#define POS_INF ( 3.402823e38f)

// ---------------- scratch ----------------
__device__ __align__(16) float g_rq[BB * RR * WD];
__device__ __align__(16) float g_newvis[BB * CC * WD];
__device__ float g_newusage[BB * CC];
__device__ int   g_topk[BB * RR * KK];
// candidates: per (b,r): 16 chunks * 8 warps * 16 = 2048
__device__ __align__(16) float g_cand_v[BB * RR * 2048];
__device__ __align__(16) int   g_cand_i[BB * RR * 2048];
// segmented argmin partials: per b: 32 segments
__device__ float g_seg_minv[BB * 32];
__device__ int   g_seg_mini[BB * 32];

// ---------------- kernel 1: projections + write-phase ----------------
__global__ void k_setup(const float* __restrict__ xi,
                        const float* __restrict__ rw,
                        const float* __restrict__ ww,
                        const float* __restrict__ usage,
                        const float* __restrict__ vis,
                        const float* __restrict__ Wrq, const float* __restrict__ brq,
                        const float* __restrict__ Wwv, const float* __restrict__ bwv,
                        const float* __restrict__ Wig, const float* __restrict__ big,
                        const float* __restrict__ Wwg, const float* __restrict__ bwg,
                        const int* __restrict__ rpos,
                        const int* __restrict__ tptr)
{
    int b = blockIdx.x;
    int t = threadIdx.x;          // 256
    int w = t >> 5, l = t & 31;
    int sub = l & 7;

    __shared__ float4 s_xi4[INS / 4];
    __shared__ float s_wv[WD];
    __shared__ float s_ig[CC];
    __shared__ float s_wg;
    __shared__ float s_ru[CC], s_rwg[CC], s_wwg[CC], s_I[CC], s_wwn[CC];
    __shared__ float s_minu;
    __shared__ int   s_p[CC];

    if (t < 64) s_xi4[t] = ((const float4*)(xi + b * INS))[t];
    __syncthreads();

    // 8 lanes cooperate per output row; 32 rows per pass, 8 passes
#pragma unroll 1
    for (int pass = 0; pass < 8; pass++) {
        int row = pass * 32 + w * 4 + (l >> 3);
        float acc = 0.f;
        if (row < 226) {
            const float4* wp;
            if (row < 128)      wp = (const float4*)(Wrq + row * INS);
            else if (row < 160) wp = (const float4*)(Wwv + (row - 128) * INS);
            else if (row < 225) wp = (const float4*)(Wig + (row - 160) * INS);
            else                wp = (const float4*)Wwg;
#pragma unroll
            for (int m = 0; m < 8; m++) {
                float4 a = wp[sub + m * 8];
                float4 q = s_xi4[sub + m * 8];
                acc += a.x * q.x + a.y * q.y + a.z * q.z + a.w * q.w;
            }
        }
        acc += __shfl_xor_sync(0xffffffffu, acc, 1);
        acc += __shfl_xor_sync(0xffffffffu, acc, 2);
        acc += __shfl_xor_sync(0xffffffffu, acc, 4);
        if (sub == 0 && row < 226) {
            if (row < 128)      g_rq[b * 128 + row] = acc + brq[row];
            else if (row < 160) s_wv[row - 128] = acc + bwv[row - 128];
            else if (row < 225) s_ig[row - 160] = 1.0f / (1.0f + expf(-(acc + big[row - 160])));
            else                s_wg = 1.0f / (1.0f + expf(-(acc + bwg[0])));
        }
    }

    int ts = tptr ? *tptr : 2;

    if (t < CC) {
        int p = rpos[b * CC + t];
        s_p[t] = p;
        float rg = rw[(size_t)b * MM + p];
        if (ts == 1) rg += 1.0f;
        s_rwg[t] = rg;
        s_wwg[t] = ww[(size_t)b * MM + p];
        s_ru[t]  = usage[(size_t)b * MM + p];
    }
    __syncthreads();
    if (t == 0) {
        float mn = s_ru[0];
        for (int c = 1; c < CC; c++) mn = fminf(mn, s_ru[c]);
        s_minu = mn;
    }
    __syncthreads();
    if (t < CC) {
        float I = (s_ru[t] == s_minu) ? 1.0f : 0.0f;
        s_I[t] = I;
        float u = ((s_rwg[t] + s_wwg[t]) > 0.005f) ? 1.0f : 0.0f;
        float nru = (u > 0.0f) ? ((float)ts - s_ru[t]) : s_ru[t];
        g_newusage[b * CC + t] = nru;
        s_wwn[t] = s_wg * (s_ig[t] * s_rwg[t] + (1.0f - s_ig[t]) * I);
    }
    __syncthreads();
    for (int idx = t; idx < CC * WD; idx += blockDim.x) {
        int c = idx >> 5, ww2 = idx & 31;
        float nv = vis[(size_t)b * CC * WD + idx] * (1.0f - s_I[c]) + s_wwn[c] * s_wv[ww2];
        g_newvis[(size_t)b * CC * WD + idx] = nv;
    }
}

// ---------------- kernel 2: fused scores + per-warp top-16 ----------------
__global__ void __launch_bounds__(256) k_scores(const float* __restrict__ memory,
                                                const int* __restrict__ rpos)
{
    int b = blockIdx.y;
    int chunk = blockIdx.x;      // 16 chunks of 4096 rows
    int t = threadIdx.x;         // 256
    int w = t >> 5, l = t & 31;
    int chunkbase = chunk * 4096;

    __shared__ float4 s_t[2048];        // 32 KB swizzled tile (256 rows)
    __shared__ float4 s_q4[RR * 8];
    __shared__ int   s_p[CC];
    __shared__ int   s_last[CC];

    if (t < RR * 8) s_q4[t] = ((const float4*)g_rq)[b * RR * 8 + t];
    if (t < CC) {
        int p = rpos[b * CC + t];
        s_p[t] = p;
    }
    __syncthreads();
    if (t < CC) {
        int lastf = 1;
        for (int c2 = t + 1; c2 < CC; c2++) if (s_p[c2] == s_p[t]) { lastf = 0; break; }
        s_last[t] = lastf;
    }

    float v0[16], v1[16], v2[16], v3[16];

#pragma unroll 1
    for (int tile = 0; tile < 16; tile++) {
        int base = chunkbase + tile * 256;
        const float4* src = (const float4*)(memory + ((size_t)b * MM + base) * WD);
        __syncthreads();   // protect s_t from previous iteration's readers
#pragma unroll
        for (int i = 0; i < 8; i++) {
            int f = i * 256 + t;
            int row = f >> 3, col = f & 7;
            s_t[row * 8 + (col ^ (row & 7))] = src[f];
        }
        __syncthreads();
        // override updated rows (last occurrence wins)
        if (t < CC && s_last[t]) {
            int p = s_p[t];
            if (p >= base && p < base + 256) {
                int loc = p - base;
                const float4* nv = (const float4*)(g_newvis + ((size_t)b * CC + t) * WD);
#pragma unroll
                for (int j = 0; j < 8; j++) s_t[loc * 8 + (j ^ (loc & 7))] = nv[j];
            }
        }
        __syncthreads();
        float a0 = 0.f, a1 = 0.f, a2 = 0.f, a3 = 0.f;
#pragma unroll
        for (int j = 0; j < 8; j++) {
            float4 x = s_t[t * 8 + (j ^ (t & 7))];
            float4 q0 = s_q4[j], q1 = s_q4[8 + j], q2 = s_q4[16 + j], q3 = s_q4[24 + j];
            a0 += x.x * q0.x + x.y * q0.y + x.z * q0.z + x.w * q0.w;
            a1 += x.x * q1.x + x.y * q1.y + x.z * q1.z + x.w * q1.w;
            a2 += x.x * q2.x + x.y * q2.y + x.z * q2.z + x.w * q2.w;
            a3 += x.x * q3.x + x.y * q3.y + x.z * q3.z + x.w * q3.w;
        }
        v0[tile] = a0; v1[tile] = a1; v2[tile] = a2; v3[tile] = a3;
    }

    // per-warp top-16 selection per r (same candidate layout as merge expects)
#define TOPK_R(vr, r)                                                                  \
    {                                                                                  \
        float* outv = g_cand_v + ((size_t)(b * RR + (r)) * 16 + chunk) * 128 + w * 16; \
        int*   outi = g_cand_i + ((size_t)(b * RR + (r)) * 16 + chunk) * 128 + w * 16; \
        for (int round = 0; round < KK; round++) {                                     \
            float bv = vr[0]; int bs = 0;                                              \
            _Pragma("unroll")                                                          \
            for (int s = 1; s < 16; s++) if (vr[s] > bv) { bv = vr[s]; bs = s; }       \
            int bi = chunkbase + bs * 256 + t;                                         \
            _Pragma("unroll")                                                          \
            for (int off = 16; off; off >>= 1) {                                       \
                float ov = __shfl_down_sync(0xffffffffu, bv, off);                     \
                int   oi = __shfl_down_sync(0xffffffffu, bi, off);                     \
                if (ov > bv || (ov == bv && oi < bi)) { bv = ov; bi = oi; }            \
            }                                                                          \
            bv = __shfl_sync(0xffffffffu, bv, 0);                                      \
            bi = __shfl_sync(0xffffffffu, bi, 0);                                      \
            if (l == 0) { outv[round] = bv; outi[round] = bi; }                        \
            int loc = bi - chunkbase;                                                  \
            if ((loc & 255) == t) {                                                    \
                int s = loc >> 8;                                                      \
                _Pragma("unroll")                                                      \
                for (int ss = 0; ss < 16; ss++) if (ss == s) vr[ss] = NEG_INF;         \
            }                                                                          \
        }                                                                              \
    }
    TOPK_R(v0, 0)
    TOPK_R(v1, 1)
    TOPK_R(v2, 2)
    TOPK_R(v3, 3)
#undef TOPK_R
}

// ---------------- kernel 3: segmented argmin over updated usage ----------------
__global__ void k_argmin_seg(const float* __restrict__ usage,
                             const int* __restrict__ rpos)
{
    int seg = blockIdx.x;  // 32 segments of 2048
    int b   = blockIdx.y;
    int t = threadIdx.x;   // 256
    int w = t >> 5, l = t & 31;

    __shared__ unsigned s_bm[64];
    __shared__ float s_wv[8];
    __shared__ int   s_wi[8];

    if (t < 64) s_bm[t] = 0u;
    __syncthreads();
    int segbase = seg * 2048;
    if (t < CC) {
        int p = rpos[b * CC + t];
        if (p >= segbase && p < segbase + 2048) {
            int loc = p - segbase;
            atomicOr(&s_bm[loc >> 5], 1u << (loc & 31));
        }
    }
    __syncthreads();

    const float4* u4 = (const float4*)(usage + (size_t)b * MM + segbase);
    float bv = POS_INF;
    int   bi = 0x7fffffff;
#pragma unroll
    for (int i = 0; i < 2; i++) {
        float4 x = u4[i * 256 + t];
        int lbase = (i * 256 + t) << 2;
        float xs[4] = {x.x, x.y, x.z, x.w};
#pragma unroll
        for (int j = 0; j < 4; j++) {
            int loc = lbase + j;
            float v = xs[j];
            if ((s_bm[loc >> 5] >> (loc & 31)) & 1u) v = POS_INF;
            int gi = segbase + loc;
            if (v < bv || (v == bv && gi < bi)) { bv = v; bi = gi; }
        }
    }
#pragma unroll
    for (int off = 16; off; off >>= 1) {
        float ov = __shfl_down_sync(0xffffffffu, bv, off);
        int   oi = __shfl_down_sync(0xffffffffu, bi, off);
        if (ov < bv || (ov == bv && oi < bi)) { bv = ov; bi = oi; }
    }
    if (l == 0) { s_wv[w] = bv; s_wi[w] = bi; }
    __syncthreads();
    if (t < 32) {
        float v = (l < 8) ? s_wv[l] : POS_INF;
        int   i = (l < 8) ? s_wi[l] : 0x7fffffff;
#pragma unroll
        for (int off = 4; off; off >>= 1) {
            float ov = __shfl_down_sync(0xffffffffu, v, off);
            int   oi = __shfl_down_sync(0xffffffffu, i, off);
            if (ov < v || (ov == v && oi < i)) { v = ov; i = oi; }
        }
        if (l == 0) { g_seg_minv[b * 32 + seg] = v; g_seg_mini[b * 32 + seg] = i; }
    }
}

// ---------------- kernel 4: merge 2048 candidates -> top-16 per (b,r) ----------------
__global__ void k_topk_merge()
{
    int br = blockIdx.x;    // 128
    int t = threadIdx.x;    // 256
    int w = t >> 5, l = t & 31;

    __shared__ float s_v[8];
    __shared__ int   s_i[8];
    __shared__ int   s_wi;

    float v[8];
    int   id[8];
    const float* cv = g_cand_v + (size_t)br * 2048;
    const int*   ci = g_cand_i + (size_t)br * 2048;
#pragma unroll
    for (int k = 0; k < 8; k++) { v[k] = cv[k * 256 + t]; id[k] = ci[k * 256 + t]; }

    for (int round = 0; round < KK; round++) {
        float bv = v[0];
        int   bi = id[0];
#pragma unroll
        for (int k = 1; k < 8; k++)
            if (v[k] > bv || (v[k] == bv && id[k] < bi)) { bv = v[k]; bi = id[k]; }
#pragma unroll
        for (int off = 16; off; off >>= 1) {
            float ov = __shfl_down_sync(0xffffffffu, bv, off);
            int   oi = __shfl_down_sync(0xffffffffu, bi, off);
            if (ov > bv || (ov == bv && oi < bi)) { bv = ov; bi = oi; }
        }
        if (l == 0) { s_v[w] = bv; s_i[w] = bi; }
        __syncthreads();
        if (t < 32) {
            float mv = (l < 8) ? s_v[l] : NEG_INF;
            int   mi = (l < 8) ? s_i[l] : 0x7fffffff;
#pragma unroll
            for (int off = 4; off; off >>= 1) {
                float ov = __shfl_down_sync(0xffffffffu, mv, off);
                int   oi = __shfl_down_sync(0xffffffffu, mi, off);
                if (ov > mv || (ov == mv && oi < mi)) { mv = ov; mi = oi; }
            }
            if (l == 0) { s_wi = mi; g_topk[br * KK + round] = mi; }
        }
        __syncthreads();
        int wi = s_wi;
#pragma unroll
        for (int k = 0; k < 8; k++) if (id[k] == wi) v[k] = NEG_INF;
        __syncthreads();
    }
}

// ---------------- kernel 5: argmin combine + gather + cosine softmax ----------------
__global__ void k_final(const float* __restrict__ memory,
                        const int* __restrict__ rpos,
                        float* __restrict__ out)
{
    int b = blockIdx.x;
    int t = threadIdx.x;   // 128

    __shared__ int   s_pos[CC];
    __shared__ int   s_rp[CC];
    __shared__ float s_vm[CC * 33];
    __shared__ float s_norm[CC];
    __shared__ float s_q[RR * WD];
    __shared__ float s_kn[RR];
    __shared__ float s_wt[RR * CC];
    __shared__ float s_v[128];
    __shared__ int   s_i[128];

    s_q[t] = g_rq[b * RR * WD + t];
    if (t < RR * KK) s_pos[t] = g_topk[b * RR * KK + t];
    if (t < CC)      s_rp[t] = rpos[b * CC + t];
    __syncthreads();

    // combine argmin: 32 segment minima + 65 overridden usage values
    {
        float v = POS_INF;
        int   i = 0x7fffffff;
        if (t < 32) { v = g_seg_minv[b * 32 + t]; i = g_seg_mini[b * 32 + t]; }
        else if (t < 32 + CC) {
            int c = t - 32;
            int p = s_rp[c];
            bool last = true;
            for (int c2 = c + 1; c2 < CC; c2++) if (s_rp[c2] == p) { last = false; break; }
            if (last) { v = g_newusage[b * CC + c]; i = p; }
        }
        s_v[t] = v; s_i[t] = i;
        __syncthreads();
        for (int s = 64; s > 0; s >>= 1) {
            if (t < s) {
                if (s_v[t + s] < s_v[t] || (s_v[t + s] == s_v[t] && s_i[t + s] < s_i[t])) {
                    s_v[t] = s_v[t + s]; s_i[t] = s_i[t + s];
                }
            }
            __syncthreads();
        }
        if (t == 0) s_pos[CC - 1] = s_i[0];
    }
    __syncthreads();

    if (t < RR) {
        float s = 0.f;
        for (int w = 0; w < WD; w++) { float q = s_q[t * WD + w]; s += q * q; }
        s_kn[t] = sqrtf(s) + 1e-6f;
    }
    if (t < CC) {
        int m = s_pos[t];
        m = min(max(m, 0), MM - 1);
        const float* row = memory + ((size_t)b * MM + m) * WD;
        for (int c2 = CC - 1; c2 >= 0; c2--)
            if (s_rp[c2] == m) { row = g_newvis + ((size_t)b * CC + c2) * WD; break; }
        float s = 0.f;
        for (int w = 0; w < WD; w++) { float v = row[w]; s_vm[t * 33 + w] = v; s += v * v; }
        s_norm[t] = sqrtf(s) + 1e-6f;
    }
    __syncthreads();

    for (int idx = t; idx < RR * CC; idx += 128) {
        int r = idx / CC, c = idx % CC;
        float num = 0.f;
        for (int w = 0; w < WD; w++) num += s_vm[c * 33 + w] * s_q[r * WD + w];
        s_wt[idx] = num / ((float)WD * s_norm[c] * s_kn[r] + 1e-6f);
    }
    __syncthreads();

    if (t < RR) {
        float mx = NEG_INF;
        for (int c = 0; c < CC; c++) mx = fmaxf(mx, s_wt[t * CC + c]);
        float sum = 0.f;
        for (int c = 0; c < CC; c++) { float e = expf(s_wt[t * CC + c] - mx); s_wt[t * CC + c] = e; sum += e; }
        float inv = 1.0f / sum;
        for (int c = 0; c < CC; c++) s_wt[t * CC + c] *= inv;
    }
    __syncthreads();

    {
        int r = t >> 5, w = t & 31;
        float acc = 0.f;
        for (int c = 0; c < CC; c++) acc += s_wt[r * CC + c] * s_vm[c * 33 + w];
        out[b * RR * WD + t] = acc;
    }
}

// ---------------- launch ----------------
extern "C" void kernel_launch(void* const* d_in, const int* in_sizes, int n_in,
                              void* d_out, int out_size)
{
    const float* xi     = (const float*)d_in[0];
    const float* memory = (const float*)d_in[1];
    const float* rw     = (const float*)d_in[2];
    const float* ww     = (const float*)d_in[3];
    const float* usage  = (const float*)d_in[4];
    const float* vis    = (const float*)d_in[5];
    const float* Wrq    = (const float*)d_in[6];
    const float* brq    = (const float*)d_in[7];
    const float* Wwv    = (const float*)d_in[8];
    const float* bwv    = (const float*)d_in[9];
    const float* Wig    = (const float*)d_in[10];
    const float* big    = (const float*)d_in[11];
    const float* Wwg    = (const float*)d_in[12];
    const float* bwg    = (const float*)d_in[13];
    const int*   rpos   = (const int*)d_in[14];
    const int*   tptr   = (n_in > 16) ? (const int*)d_in[16] : nullptr;

    k_setup<<<BB, 256>>>(xi, rw, ww, usage, vis, Wrq, brq, Wwv, bwv,
                         Wig, big, Wwg, bwg, rpos, tptr);
    k_scores<<<dim3(16, BB), 256>>>(memory, rpos);
    k_argmin_seg<<<dim3(32, BB), 256>>>(usage, rpos);
    k_topk_merge<<<BB * RR, 256>>>();
    k_final<<<BB, 128>>>(memory, rpos, (float*)d_out);
}

// round 4
// speedup vs baseline: 3.8090x; 1.1298x over previous
#include <cuda_runtime.h>
#include <math.h>
#include <stdint.h>

#define BB  32
#define MM  65536
#define WD  32
#define RR  4
#define KK  16
#define CC  65
#define INS 256
#define NEG_INF (-3.402823e38f)
#define POS_INF ( 3.402823e38f)
#define FULLMASK 0xffffffffu

// ---------------- scratch ----------------
__device__ __align__(16) float g_rq[BB * RR * WD];
__device__ __align__(16) float g_newvis[BB * CC * WD];
__device__ float g_newusage[BB * CC];
__device__ int   g_topk[BB * RR * KK];
// candidates: per (b,r): 32 chunks * 16 = 512
__device__ __align__(16) unsigned g_cand_v[BB * RR * 512];
__device__ __align__(16) int      g_cand_i[BB * RR * 512];
// segmented argmin partials: per b: 32 segments
__device__ float g_seg_minv[BB * 32];
__device__ int   g_seg_mini[BB * 32];

// order-preserving float -> u32 map (greater float <-> greater uint)
__device__ __forceinline__ unsigned fmap(float x) {
    unsigned u = __float_as_uint(x);
    return (u & 0x80000000u) ? ~u : (u | 0x80000000u);
}

__device__ __forceinline__ void cp_async16(void* smem_dst, const void* gsrc) {
    unsigned sa = (unsigned)__cvta_generic_to_shared(smem_dst);
    asm volatile("cp.async.cg.shared.global [%0], [%1], 16;\n" :: "r"(sa), "l"(gsrc));
}
#define CP_COMMIT() asm volatile("cp.async.commit_group;\n" ::: "memory")
#define CP_WAIT1()  asm volatile("cp.async.wait_group 1;\n" ::: "memory")

// ---------------- kernel 1: projections + write-phase ----------------
__global__ void k_setup(const float* __restrict__ xi,
                        const float* __restrict__ rw,
                        const float* __restrict__ ww,
                        const float* __restrict__ usage,
                        const float* __restrict__ vis,
                        const float* __restrict__ Wrq, const float* __restrict__ brq,
                        const float* __restrict__ Wwv, const float* __restrict__ bwv,
                        const float* __restrict__ Wig, const float* __restrict__ big,
                        const float* __restrict__ Wwg, const float* __restrict__ bwg,
                        const int* __restrict__ rpos,
                        const int* __restrict__ tptr)
{
    int b = blockIdx.x;
    int t = threadIdx.x;          // 256
    int w = t >> 5, l = t & 31;
    int sub = l & 7;

    __shared__ float4 s_xi4[INS / 4];
    __shared__ float s_wv[WD];
    __shared__ float s_ig[CC];
    __shared__ float s_wg;
    __shared__ float s_ru[CC], s_rwg[CC], s_wwg[CC], s_I[CC], s_wwn[CC];
    __shared__ float s_minu;
    __shared__ int   s_p[CC];

    if (t < 64) s_xi4[t] = ((const float4*)(xi + b * INS))[t];
    __syncthreads();

#pragma unroll 1
    for (int pass = 0; pass < 8; pass++) {
        int row = pass * 32 + w * 4 + (l >> 3);
        float acc = 0.f;
        if (row < 226) {
            const float4* wp;
            if (row < 128)      wp = (const float4*)(Wrq + row * INS);
            else if (row < 160) wp = (const float4*)(Wwv + (row - 128) * INS);
            else if (row < 225) wp = (const float4*)(Wig + (row - 160) * INS);
            else                wp = (const float4*)Wwg;
#pragma unroll
            for (int m = 0; m < 8; m++) {
                float4 a = wp[sub + m * 8];
                float4 q = s_xi4[sub + m * 8];
                acc += a.x * q.x + a.y * q.y + a.z * q.z + a.w * q.w;
            }
        }
        acc += __shfl_xor_sync(0xffffffffu, acc, 1);
        acc += __shfl_xor_sync(0xffffffffu, acc, 2);
        acc += __shfl_xor_sync(0xffffffffu, acc, 4);
        if (sub == 0 && row < 226) {
            if (row < 128)      g_rq[b * 128 + row] = acc + brq[row];
            else if (row < 160) s_wv[row - 128] = acc + bwv[row - 128];
            else if (row < 225) s_ig[row - 160] = 1.0f / (1.0f + expf(-(acc + big[row - 160])));
            else                s_wg = 1.0f / (1.0f + expf(-(acc + bwg[0])));
        }
    }

    int ts = tptr ? *tptr : 2;

    if (t < CC) {
        int p = rpos[b * CC + t];
        s_p[t] = p;
        float rg = rw[(size_t)b * MM + p];
        if (ts == 1) rg += 1.0f;
        s_rwg[t] = rg;
        s_wwg[t] = ww[(size_t)b * MM + p];
        s_ru[t]  = usage[(size_t)b * MM + p];
    }
    __syncthreads();
    if (t == 0) {
        float mn = s_ru[0];
        for (int c = 1; c < CC; c++) mn = fminf(mn, s_ru[c]);
        s_minu = mn;
    }
    __syncthreads();
    if (t < CC) {
        float I = (s_ru[t] == s_minu) ? 1.0f : 0.0f;
        s_I[t] = I;
        float u = ((s_rwg[t] + s_wwg[t]) > 0.005f) ? 1.0f : 0.0f;
        float nru = (u > 0.0f) ? ((float)ts - s_ru[t]) : s_ru[t];
        g_newusage[b * CC + t] = nru;
        s_wwn[t] = s_wg * (s_ig[t] * s_rwg[t] + (1.0f - s_ig[t]) * I);
    }
    __syncthreads();
    for (int idx = t; idx < CC * WD; idx += blockDim.x) {
        int c = idx >> 5, ww2 = idx & 31;
        float nv = vis[(size_t)b * CC * WD + idx] * (1.0f - s_I[c]) + s_wwn[c] * s_wv[ww2];
        g_newvis[(size_t)b * CC * WD + idx] = nv;
    }
}

// ---------------- block-level top-16 selection over 2048-row chunk ----------------
// u[16]: per-thread mapped scores; rowloc = slot*128 + t
__device__ __forceinline__ void select16(unsigned (&u)[16], int t, int w, int l,
                                         int chunkbase,
                                         unsigned* s_wm, unsigned* s_wk, unsigned* s_bk,
                                         unsigned* outv, int* outi)
{
    unsigned lm = u[0];
    unsigned lkey = (unsigned)t;
#pragma unroll
    for (int s = 1; s < 16; s++)
        if (u[s] > lm) { lm = u[s]; lkey = (unsigned)(s * 128 + t); }

    for (int round = 0; round < 16; round++) {
        int par = round & 1;
        unsigned m_w = __reduce_max_sync(FULLMASK, lm);
        unsigned key = (lm == m_w) ? lkey : 0xffffffffu;
        unsigned k_w = __reduce_min_sync(FULLMASK, key);
        if (l == 0) { s_wm[par * 4 + w] = m_w; s_wk[par * 4 + w] = k_w; }
        __syncthreads();
        if (t == 0) {
            unsigned bm = s_wm[par * 4], bk = s_wk[par * 4];
#pragma unroll
            for (int w2 = 1; w2 < 4; w2++) {
                unsigned vm2 = s_wm[par * 4 + w2], vk2 = s_wk[par * 4 + w2];
                if (vm2 > bm || (vm2 == bm && vk2 < bk)) { bm = vm2; bk = vk2; }
            }
            s_bk[par] = bk;
            outv[round] = bm;
            outi[round] = chunkbase + (int)bk;
        }
        __syncthreads();
        unsigned bk = s_bk[par];
        if ((bk & 127u) == (unsigned)t) {
            int slot = (int)(bk >> 7);
#pragma unroll
            for (int s = 0; s < 16; s++) if (s == slot) u[s] = 0u;
            lm = u[0]; lkey = (unsigned)t;
#pragma unroll
            for (int s = 1; s < 16; s++)
                if (u[s] > lm) { lm = u[s]; lkey = (unsigned)(s * 128 + t); }
        }
    }
}

// ---------------- kernel 2: cp.async pipelined scores + block top-16 ----------------
__global__ void __launch_bounds__(128, 4) k_scores(const float* __restrict__ memory,
                                                   const int* __restrict__ rpos)
{
    int b = blockIdx.y;
    int chunk = blockIdx.x;      // 32 chunks of 2048 rows
    int t = threadIdx.x;         // 128
    int w = t >> 5, l = t & 31;
    int chunkbase = chunk * 2048;

    __shared__ float4 s_t[2][128 * 8];   // two 16 KB tiles, swizzled
    __shared__ float4 s_q4[RR * 8];
    __shared__ int   s_p[CC];
    __shared__ int   s_last[CC];
    __shared__ unsigned s_wm[8], s_wk[8], s_bk[2];

    if (t < RR * 8) s_q4[t] = ((const float4*)g_rq)[b * RR * 8 + t];
    if (t < CC)     s_p[t] = rpos[b * CC + t];
    __syncthreads();
    if (t < CC) {
        int lastf = 1;
        for (int c2 = t + 1; c2 < CC; c2++) if (s_p[c2] == s_p[t]) { lastf = 0; break; }
        s_last[t] = lastf;
    }

    unsigned u0[16], u1[16], u2[16], u3[16];

    const float* gbase = memory + ((size_t)b * MM + chunkbase) * WD;

    // prologue: tile 0
    {
        const float4* src = (const float4*)gbase;
#pragma unroll
        for (int j = 0; j < 8; j++) {
            int f = j * 128 + t;
            int row = f >> 3, col = f & 7;
            cp_async16(&s_t[0][row * 8 + (col ^ (row & 7))], src + f);
        }
        CP_COMMIT();
    }

#pragma unroll
    for (int tile = 0; tile < 16; tile++) {
        int buf = tile & 1;
        __syncthreads();   // everyone done reading buf^1 (2 iters ago)
        if (tile < 15) {
            const float4* src = (const float4*)(gbase + (size_t)(tile + 1) * 128 * WD);
#pragma unroll
            for (int j = 0; j < 8; j++) {
                int f = j * 128 + t;
                int row = f >> 3, col = f & 7;
                cp_async16(&s_t[buf ^ 1][row * 8 + (col ^ (row & 7))], src + f);
            }
        }
        CP_COMMIT();
        CP_WAIT1();        // current tile's group complete (this thread)
        __syncthreads();   // ... and visible block-wide
        int base = chunkbase + tile * 128;
        if (t < CC && s_last[t]) {
            int p = s_p[t];
            if (p >= base && p < base + 128) {
                int loc = p - base;
                const float4* nv = (const float4*)(g_newvis + ((size_t)b * CC + t) * WD);
#pragma unroll
                for (int j = 0; j < 8; j++) s_t[buf][loc * 8 + (j ^ (loc & 7))] = nv[j];
            }
        }
        __syncthreads();
        float a0 = 0.f, a1 = 0.f, a2 = 0.f, a3 = 0.f;
#pragma unroll
        for (int j = 0; j < 8; j++) {
            float4 x = s_t[buf][t * 8 + (j ^ (t & 7))];
            float4 q0 = s_q4[j], q1 = s_q4[8 + j], q2 = s_q4[16 + j], q3 = s_q4[24 + j];
            a0 += x.x * q0.x + x.y * q0.y + x.z * q0.z + x.w * q0.w;
            a1 += x.x * q1.x + x.y * q1.y + x.z * q1.z + x.w * q1.w;
            a2 += x.x * q2.x + x.y * q2.y + x.z * q2.z + x.w * q2.w;
            a3 += x.x * q3.x + x.y * q3.y + x.z * q3.z + x.w * q3.w;
        }
        u0[tile] = fmap(a0); u1[tile] = fmap(a1);
        u2[tile] = fmap(a2); u3[tile] = fmap(a3);
    }

    // block-level top-16 per r
    {
        unsigned* bv = g_cand_v + ((size_t)(b * RR) * 32 + chunk) * 16;
        int*      bi = g_cand_i + ((size_t)(b * RR) * 32 + chunk) * 16;
        select16(u0, t, w, l, chunkbase, s_wm, s_wk, s_bk, bv,            bi);
        select16(u1, t, w, l, chunkbase, s_wm, s_wk, s_bk, bv + 32 * 16,  bi + 32 * 16);
        select16(u2, t, w, l, chunkbase, s_wm, s_wk, s_bk, bv + 64 * 16,  bi + 64 * 16);
        select16(u3, t, w, l, chunkbase, s_wm, s_wk, s_bk, bv + 96 * 16,  bi + 96 * 16);
    }
}

// ---------------- kernel 3: segmented argmin over updated usage ----------------
__global__ void k_argmin_seg(const float* __restrict__ usage,
                             const int* __restrict__ rpos)
{
    int seg = blockIdx.x;  // 32 segments of 2048
    int b   = blockIdx.y;
    int t = threadIdx.x;   // 256
    int w = t >> 5, l = t & 31;

    __shared__ unsigned s_bm[64];
    __shared__ float s_wv[8];
    __shared__ int   s_wi[8];

    if (t < 64) s_bm[t] = 0u;
    __syncthreads();
    int segbase = seg * 2048;
    if (t < CC) {
        int p = rpos[b * CC + t];
        if (p >= segbase && p < segbase + 2048) {
            int loc = p - segbase;
            atomicOr(&s_bm[loc >> 5], 1u << (loc & 31));
        }
    }
    __syncthreads();

    const float4* u4 = (const float4*)(usage + (size_t)b * MM + segbase);
    float bv = POS_INF;
    int   bi = 0x7fffffff;
#pragma unroll
    for (int i = 0; i < 2; i++) {
        float4 x = u4[i * 256 + t];
        int lbase = (i * 256 + t) << 2;
        float xs[4] = {x.x, x.y, x.z, x.w};
#pragma unroll
        for (int j = 0; j < 4; j++) {
            int loc = lbase + j;
            float v = xs[j];
            if ((s_bm[loc >> 5] >> (loc & 31)) & 1u) v = POS_INF;
            int gi = segbase + loc;
            if (v < bv || (v == bv && gi < bi)) { bv = v; bi = gi; }
        }
    }
#pragma unroll
    for (int off = 16; off; off >>= 1) {
        float ov = __shfl_down_sync(0xffffffffu, bv, off);
        int   oi = __shfl_down_sync(0xffffffffu, bi, off);
        if (ov < bv || (ov == bv && oi < bi)) { bv = ov; bi = oi; }
    }
    if (l == 0) { s_wv[w] = bv; s_wi[w] = bi; }
    __syncthreads();
    if (t < 32) {
        float v = (l < 8) ? s_wv[l] : POS_INF;
        int   i = (l < 8) ? s_wi[l] : 0x7fffffff;
#pragma unroll
        for (int off = 4; off; off >>= 1) {
            float ov = __shfl_down_sync(0xffffffffu, v, off);
            int   oi = __shfl_down_sync(0xffffffffu, i, off);
            if (ov < v || (ov == v && oi < i)) { v = ov; i = oi; }
        }
        if (l == 0) { g_seg_minv[b * 32 + seg] = v; g_seg_mini[b * 32 + seg] = i; }
    }
}

// ---------------- kernel 4: merge 512 candidates -> top-16 per (b,r) ----------------
__global__ void k_topk_merge()
{
    int br = blockIdx.x;    // 128
    int t = threadIdx.x;    // 256
    int w = t >> 5, l = t & 31;

    __shared__ unsigned s_wm[16], s_wk[16];
    __shared__ unsigned s_bm2[2], s_bk2[2];

    const unsigned* cv = g_cand_v + (size_t)br * 512;
    const int*      ci = g_cand_i + (size_t)br * 512;
    unsigned v0 = cv[t],       v1 = cv[256 + t];
    unsigned i0 = (unsigned)ci[t], i1 = (unsigned)ci[256 + t];

    for (int round = 0; round < 16; round++) {
        int par = round & 1;
        unsigned lv, li;
        if (v0 > v1 || (v0 == v1 && i0 < i1)) { lv = v0; li = i0; }
        else                                  { lv = v1; li = i1; }
        unsigned m_w = __reduce_max_sync(FULLMASK, lv);
        unsigned key = (lv == m_w) ? li : 0xffffffffu;
        unsigned k_w = __reduce_min_sync(FULLMASK, key);
        if (l == 0) { s_wm[par * 8 + w] = m_w; s_wk[par * 8 + w] = k_w; }
        __syncthreads();
        if (t == 0) {
            unsigned bm = s_wm[par * 8], bk = s_wk[par * 8];
#pragma unroll
            for (int w2 = 1; w2 < 8; w2++) {
                unsigned vm2 = s_wm[par * 8 + w2], vk2 = s_wk[par * 8 + w2];
                if (vm2 > bm || (vm2 == bm && vk2 < bk)) { bm = vm2; bk = vk2; }
            }
            s_bm2[par] = bm; s_bk2[par] = bk;
            g_topk[br * KK + round] = (int)bk;
        }
        __syncthreads();
        unsigned bk = s_bk2[par];
        if (i0 == bk) v0 = 0u;
        if (i1 == bk) v1 = 0u;
    }
}

// ---------------- kernel 5: argmin combine + gather + cosine softmax ----------------
__global__ void k_final(const float* __restrict__ memory,
                        const int* __restrict__ rpos,
                        float* __restrict__ out)
{
    int b = blockIdx.x;
    int t = threadIdx.x;   // 128

    __shared__ int   s_pos[CC];
    __shared__ int   s_rp[CC];
    __shared__ float s_vm[CC * 33];
    __shared__ float s_norm[CC];
    __shared__ float s_q[RR * WD];
    __shared__ float s_kn[RR];
    __shared__ float s_wt[RR * CC];
    __shared__ float s_v[128];
    __shared__ int   s_i[128];

    s_q[t] = g_rq[b * RR * WD + t];
    if (t < RR * KK) s_pos[t] = g_topk[b * RR * KK + t];
    if (t < CC)      s_rp[t] = rpos[b * CC + t];
    __syncthreads();

    // combine argmin: 32 segment minima + 65 overridden usage values
    {
        float v = POS_INF;
        int   i = 0x7fffffff;
        if (t < 32) { v = g_seg_minv[b * 32 + t]; i = g_seg_mini[b * 32 + t]; }
        else if (t < 32 + CC) {
            int c = t - 32;
            int p = s_rp[c];
            bool last = true;
            for (int c2 = c + 1; c2 < CC; c2++) if (s_rp[c2] == p) { last = false; break; }
            if (last) { v = g_newusage[b * CC + c]; i = p; }
        }
        s_v[t] = v; s_i[t] = i;
        __syncthreads();
        for (int s = 64; s > 0; s >>= 1) {
            if (t < s) {
                if (s_v[t + s] < s_v[t] || (s_v[t + s] == s_v[t] && s_i[t + s] < s_i[t])) {
                    s_v[t] = s_v[t + s]; s_i[t] = s_i[t + s];
                }
            }
            __syncthreads();
        }
        if (t == 0) s_pos[CC - 1] = s_i[0];
    }
    __syncthreads();

    if (t < RR) {
        float s = 0.f;
        for (int w = 0; w < WD; w++) { float q = s_q[t * WD + w]; s += q * q; }
        s_kn[t] = sqrtf(s) + 1e-6f;
    }
    if (t < CC) {
        int m = s_pos[t];
        m = min(max(m, 0), MM - 1);
        const float* row = memory + ((size_t)b * MM + m) * WD;
        for (int c2 = CC - 1; c2 >= 0; c2--)
            if (s_rp[c2] == m) { row = g_newvis + ((size_t)b * CC + c2) * WD; break; }
        float s = 0.f;
        for (int w = 0; w < WD; w++) { float v = row[w]; s_vm[t * 33 + w] = v; s += v * v; }
        s_norm[t] = sqrtf(s) + 1e-6f;
    }
    __syncthreads();

    for (int idx = t; idx < RR * CC; idx += 128) {
        int r = idx / CC, c = idx % CC;
        float num = 0.f;
        for (int w = 0; w < WD; w++) num += s_vm[c * 33 + w] * s_q[r * WD + w];
        s_wt[idx] = num / ((float)WD * s_norm[c] * s_kn[r] + 1e-6f);
    }
    __syncthreads();

    if (t < RR) {
        float mx = NEG_INF;
        for (int c = 0; c < CC; c++) mx = fmaxf(mx, s_wt[t * CC + c]);
        float sum = 0.f;
        for (int c = 0; c < CC; c++) { float e = expf(s_wt[t * CC + c] - mx); s_wt[t * CC + c] = e; sum += e; }
        float inv = 1.0f / sum;
        for (int c = 0; c < CC; c++) s_wt[t * CC + c] *= inv;
    }
    __syncthreads();

    {
        int r = t >> 5, w = t & 31;
        float acc = 0.f;
        for (int c = 0; c < CC; c++) acc += s_wt[r * CC + c] * s_vm[c * 33 + w];
        out[b * RR * WD + t] = acc;
    }
}

// ---------------- launch ----------------
extern "C" void kernel_launch(void* const* d_in, const int* in_sizes, int n_in,
                              void* d_out, int out_size)
{
    const float* xi     = (const float*)d_in[0];
    const float* memory = (const float*)d_in[1];
    const float* rw     = (const float*)d_in[2];
    const float* ww     = (const float*)d_in[3];
    const float* usage  = (const float*)d_in[4];
    const float* vis    = (const float*)d_in[5];
    const float* Wrq    = (const float*)d_in[6];
    const float* brq    = (const float*)d_in[7];
    const float* Wwv    = (const float*)d_in[8];
    const float* bwv    = (const float*)d_in[9];
    const float* Wig    = (const float*)d_in[10];
    const float* big    = (const float*)d_in[11];
    const float* Wwg    = (const float*)d_in[12];
    const float* bwg    = (const float*)d_in[13];
    const int*   rpos   = (const int*)d_in[14];
    const int*   tptr   = (n_in > 16) ? (const int*)d_in[16] : nullptr;

    k_setup<<<BB, 256>>>(xi, rw, ww, usage, vis, Wrq, brq, Wwv, bwv,
                         Wig, big, Wwg, bwg, rpos, tptr);
    k_scores<<<dim3(32, BB), 128>>>(memory, rpos);
    k_argmin_seg<<<dim3(32, BB), 256>>>(usage, rpos);
    k_topk_merge<<<BB * RR, 256>>>();
    k_final<<<BB, 128>>>(memory, rpos, (float*)d_out);
}